// round 1
// baseline (speedup 1.0000x reference)
#include <cuda_runtime.h>

// Problem constants (fixed by reference: points shape (4, 8192, 3) fp32)
#define BATCH    4
#define NPTS     8192
#define NN_SIZE  16
#define NK       17          // 16 neighbors + self slot
#define RADIUS2  0.25f
#define EPS      1e-4f

#define BLOCK    128
#define TILE     2048        // candidates per smem tile (24 KB)

__global__ void zero_out_kernel(float* out) {
    if (threadIdx.x == 0) out[0] = 0.0f;
}

__global__ void __launch_bounds__(BLOCK)
repulsion_loss_kernel(const float* __restrict__ pts, float* __restrict__ out) {
    __shared__ __align__(16) float tile[TILE * 3];

    const int qidx = blockIdx.x * BLOCK + threadIdx.x;      // global point id in [0, B*N)
    const int b    = blockIdx.x / (NPTS / BLOCK);           // batch id
    const float* __restrict__ bpts = pts + (size_t)b * NPTS * 3;

    // Query point (register resident)
    const float qx = pts[qidx * 3 + 0];
    const float qy = pts[qidx * 3 + 1];
    const float qz = pts[qidx * 3 + 2];

    // Sorted ascending top-NK array, capped at RADIUS2 (sentinel -> f()==0).
    float a[NK];
#pragma unroll
    for (int k = 0; k < NK; ++k) a[k] = RADIUS2;

    for (int t0 = 0; t0 < NPTS; t0 += TILE) {
        // Cooperative vectorized tile load: TILE*3 floats = 1536 float4
        {
            const float4* __restrict__ src = (const float4*)(bpts + t0 * 3);
            float4* dst = (float4*)tile;
#pragma unroll
            for (int i = threadIdx.x; i < TILE * 3 / 4; i += BLOCK)
                dst[i] = src[i];
        }
        __syncthreads();

#pragma unroll 4
        for (int j = 0; j < TILE; ++j) {
            // All lanes read the same candidate -> broadcast LDS, conflict-free
            const float dx = qx - tile[3 * j + 0];
            const float dy = qy - tile[3 * j + 1];
            const float dz = qz - tile[3 * j + 2];
            const float d2 = fmaf(dx, dx, fmaf(dy, dy, dz * dz));

            if (d2 < a[NK - 1]) {
                // Branchless sorted insert (drop current max):
                // b[k] = (v < a[k]) ? max(v, a[k-1]) : a[k]
#pragma unroll
                for (int k = NK - 1; k > 0; --k)
                    a[k] = (d2 < a[k]) ? fmaxf(d2, a[k - 1]) : a[k];
                a[0] = fminf(a[0], d2);
            }
        }
        __syncthreads();
    }

    // a[0] == 0 is the query itself (exact-bits subtraction). Sum f over a[1..16].
    float s = 0.0f;
#pragma unroll
    for (int k = 1; k < NK; ++k) {
        const float v = a[k];
        if (v < RADIUS2) s += rsqrtf(v + EPS);
    }
    s *= (1.0f / (float)(BATCH * NPTS * NN_SIZE));   // fold in the mean

    // Block reduction -> atomicAdd
#pragma unroll
    for (int off = 16; off > 0; off >>= 1)
        s += __shfl_xor_sync(0xFFFFFFFFu, s, off);

    __shared__ float wsum[BLOCK / 32];
    const int lane = threadIdx.x & 31;
    const int wid  = threadIdx.x >> 5;
    if (lane == 0) wsum[wid] = s;
    __syncthreads();
    if (threadIdx.x == 0) {
        float t = 0.0f;
#pragma unroll
        for (int w = 0; w < BLOCK / 32; ++w) t += wsum[w];
        atomicAdd(out, t);
    }
}

extern "C" void kernel_launch(void* const* d_in, const int* in_sizes, int n_in,
                              void* d_out, int out_size) {
    const float* pts = (const float*)d_in[0];
    float* out = (float*)d_out;
    zero_out_kernel<<<1, 32>>>(out);
    repulsion_loss_kernel<<<(BATCH * NPTS) / BLOCK, BLOCK>>>(pts, out);
}

// round 3
// speedup vs baseline: 2.0409x; 2.0409x over previous
#include <cuda_runtime.h>

// Problem constants (fixed: points shape (4, 8192, 3) fp32)
#define BATCH    4
#define NPTS     8192
#define NQ_TOT   (BATCH * NPTS)     // 32768
#define NN_SIZE  16
#define NK       17                  // 16 neighbors + self slot
#define RADIUS2  0.25f
#define EPS      1e-4f

#define SPLITS   8
#define CHUNK    (NPTS / SPLITS)     // 1024 candidates per block
#define BLOCK    128
#define CAP      128                 // per-thread per-chunk within-radius buffer

// Partial sorted top-NK arrays: [chunk][slot][query] for coalesced access.
__device__ float g_scratch[SPLITS * NK * NQ_TOT];   // 17.8 MB static scratch

__global__ void zero_out_kernel(float* out) {
    if (threadIdx.x == 0) out[0] = 0.0f;
}

// Pass 1: each block = (128 queries) x (one 1024-candidate chunk).
// Emits the chunk-local capped top-17 d^2 per query.
__global__ void __launch_bounds__(BLOCK)
knn_chunk_kernel(const float* __restrict__ pts) {
    __shared__ __align__(16) float4 tile[CHUNK];    // (x, y, z, |c|^2) : 16 KB

    const int qidx  = blockIdx.x * BLOCK + threadIdx.x;   // [0, NQ_TOT)
    const int chunk = blockIdx.y;
    const int b     = blockIdx.x / (NPTS / BLOCK);
    const float* __restrict__ bpts = pts + (size_t)b * NPTS * 3;

    // Load chunk into smem with precomputed squared norm
    for (int i = threadIdx.x; i < CHUNK; i += BLOCK) {
        const float* p = bpts + (chunk * CHUNK + i) * 3;
        const float x = p[0], y = p[1], z = p[2];
        tile[i] = make_float4(x, y, z, fmaf(x, x, fmaf(y, y, z * z)));
    }

    // Query registers
    const float qx = pts[qidx * 3 + 0];
    const float qy = pts[qidx * 3 + 1];
    const float qz = pts[qidx * 3 + 2];
    const float qs  = fmaf(qx, qx, fmaf(qy, qy, qz * qz));
    const float m2x = -2.0f * qx, m2y = -2.0f * qy, m2z = -2.0f * qz;

    __syncthreads();

    // Hot loop: filter within-radius candidates into a per-thread buffer.
    // d^2 = |q|^2 + |c|^2 - 2 q.c  (matches reference formula)
    float buf[CAP];      // local memory (dynamic index), per-thread strided
    int   cnt = 0;
#pragma unroll 8
    for (int j = 0; j < CHUNK; ++j) {
        const float4 c = tile[j];
        float t = qs + c.w;
        t = fmaf(m2x, c.x, t);
        t = fmaf(m2y, c.y, t);
        t = fmaf(m2z, c.z, t);
        if (t < RADIUS2) {
            if (cnt < CAP) buf[cnt] = t;
            ++cnt;
        }
    }
    if (cnt > CAP) cnt = CAP;

    // Build sorted ascending top-NK (capped at RADIUS2) from the buffer.
    float a[NK];
#pragma unroll
    for (int k = 0; k < NK; ++k) a[k] = RADIUS2;
    for (int i = 0; i < cnt; ++i) {
        const float v = buf[i];
#pragma unroll
        for (int k = NK - 1; k > 0; --k)
            a[k] = (v < a[k]) ? fmaxf(v, a[k - 1]) : a[k];
        a[0] = fminf(a[0], v);
    }

    // Coalesced scatter: slot-major layout
#pragma unroll
    for (int k = 0; k < NK; ++k)
        g_scratch[(chunk * NK + k) * NQ_TOT + qidx] = a[k];
}

// Pass 2: merge the SPLITS sorted partials per query, apply f, reduce.
__global__ void __launch_bounds__(BLOCK)
merge_kernel(float* __restrict__ out) {
    const int qidx = blockIdx.x * BLOCK + threadIdx.x;

    float m[NK];
#pragma unroll
    for (int k = 0; k < NK; ++k) m[k] = RADIUS2;

    for (int c = 0; c < SPLITS; ++c) {
        const float* __restrict__ base = g_scratch + (size_t)(c * NK) * NQ_TOT + qidx;
#pragma unroll
        for (int k = 0; k < NK; ++k) {
            const float v = base[k * NQ_TOT];
            if (v >= m[NK - 1]) break;   // chunk array sorted ascending
#pragma unroll
            for (int t = NK - 1; t > 0; --t)
                m[t] = (v < m[t]) ? fmaxf(v, m[t - 1]) : m[t];
            m[0] = fminf(m[0], v);
        }
    }

    // m[0] is the query itself (d^2 ~ 0, global minimum). Sum f over m[1..16].
    float s = 0.0f;
#pragma unroll
    for (int k = 1; k < NK; ++k) {
        const float v = m[k];
        if (v < RADIUS2) s += rsqrtf(v + EPS);
    }
    s *= (1.0f / (float)(NQ_TOT * NN_SIZE));   // fold in the mean

    // Warp + block reduction -> atomicAdd
#pragma unroll
    for (int off = 16; off > 0; off >>= 1)
        s += __shfl_xor_sync(0xFFFFFFFFu, s, off);

    __shared__ float wsum[BLOCK / 32];
    const int lane = threadIdx.x & 31;
    const int wid  = threadIdx.x >> 5;
    if (lane == 0) wsum[wid] = s;
    __syncthreads();
    if (threadIdx.x == 0) {
        float t = 0.0f;
#pragma unroll
        for (int w = 0; w < BLOCK / 32; ++w) t += wsum[w];
        atomicAdd(out, t);
    }
}

extern "C" void kernel_launch(void* const* d_in, const int* in_sizes, int n_in,
                              void* d_out, int out_size) {
    const float* pts = (const float*)d_in[0];
    float* out = (float*)d_out;

    zero_out_kernel<<<1, 32>>>(out);

    dim3 grid1(NQ_TOT / BLOCK, SPLITS);
    knn_chunk_kernel<<<grid1, BLOCK>>>(pts);

    merge_kernel<<<NQ_TOT / BLOCK, BLOCK>>>(out);
}